// round 1
// baseline (speedup 1.0000x reference)
#include <cuda_runtime.h>
#include <cstdint>

#define BB 4
#define SS 1024
#define HH 32
#define DD 8
#define EE 256
constexpr int NROWS = BB * SS * HH;   // 131072 quantum rows

// Scratch (allocation-free rule: __device__ globals)
__device__ float g_qh[BB * HH * SS * DD];   // [B,H,S,D] head-major, 4 MB
__device__ float g_att[BB * SS * EE];       // [B,S,E] attention out, 4 MB

// ---------- packed f32x2 helpers (Blackwell dual FP32 datapath) ----------
__device__ __forceinline__ unsigned long long pack2(float lo, float hi) {
    unsigned long long r;
    asm("mov.b64 %0, {%1, %2};" : "=l"(r) : "f"(lo), "f"(hi));
    return r;
}
__device__ __forceinline__ void unpack2(unsigned long long v, float& lo, float& hi) {
    asm("mov.b64 {%0, %1}, %2;" : "=f"(lo), "=f"(hi) : "l"(v));
}
__device__ __forceinline__ unsigned long long ffma2(unsigned long long a,
                                                    unsigned long long b,
                                                    unsigned long long c) {
    unsigned long long d;
    asm("fma.rn.f32x2 %0, %1, %2, %3;" : "=l"(d) : "l"(a), "l"(b), "l"(c));
    return d;
}
__device__ __forceinline__ float ex2(float x) {
    float y;
    asm("ex2.approx.ftz.f32 %0, %1;" : "=f"(y) : "f"(x));
    return y;
}

// ---------------------------------------------------------------------------
// Kernel 1: quantum heads via closed form.
// After the CNOT ring, <Z_w> = prod_{j=0..w} cos(a_j) (w>=1),
// <Z_0> = prod_{j=1..7} cos(a_j),  a_j = x_j + theta_j.
// Writes head-major layout [B,H,S,D] for the attention kernel.
// ---------------------------------------------------------------------------
__global__ void qheads_kernel(const float* __restrict__ x,
                              const float* __restrict__ theta) {
    int n = blockIdx.x * blockDim.x + threadIdx.x;
    if (n >= NROWS) return;

    float4 xa = *reinterpret_cast<const float4*>(x + (size_t)n * DD);
    float4 xb = *reinterpret_cast<const float4*>(x + (size_t)n * DD + 4);

    float c[8];
    c[0] = cosf(xa.x + theta[0]);
    c[1] = cosf(xa.y + theta[1]);
    c[2] = cosf(xa.z + theta[2]);
    c[3] = cosf(xa.w + theta[3]);
    c[4] = cosf(xb.x + theta[4]);
    c[5] = cosf(xb.y + theta[5]);
    c[6] = cosf(xb.z + theta[6]);
    c[7] = cosf(xb.w + theta[7]);

    float z[8];
    float p = c[0];
#pragma unroll
    for (int w = 1; w < 8; w++) { p *= c[w]; z[w] = p; }
    float s = c[7];
#pragma unroll
    for (int w = 6; w >= 1; w--) s *= c[w];
    z[0] = s;

    // n = (b*S + s)*H + h  ->  write at [b, h, s, :]
    int h  = n % HH;
    int bs = n / HH;
    int b  = bs / SS;
    int si = bs % SS;
    float* dst = g_qh + ((((size_t)b * HH + h) * SS + si) * DD);
    *reinterpret_cast<float4*>(dst)     = make_float4(z[0], z[1], z[2], z[3]);
    *reinterpret_cast<float4*>(dst + 4) = make_float4(z[4], z[5], z[6], z[7]);
}

// ---------------------------------------------------------------------------
// Kernel 2: attention per head. K(=Q=V) for one head = 1024x8 fp32 = 32 KB,
// staged entirely in SMEM. One thread per query, streaming over keys with
// SMEM broadcast. |score| <= sqrt(8), so softmax needs no max subtraction.
// Inner loop uses packed f32x2 FMAs (2x fp32 throughput on Blackwell).
// ---------------------------------------------------------------------------
__global__ void __launch_bounds__(128) attn_kernel() {
    __shared__ float sK[SS * DD];   // 32 KB

    int bh  = blockIdx.x;           // 0..127 (b*32 + h)
    int tid = threadIdx.x;

    const float4* src = reinterpret_cast<const float4*>(g_qh + (size_t)bh * SS * DD);
    float4* s4 = reinterpret_cast<float4*>(sK);
#pragma unroll
    for (int i = tid; i < SS * DD / 4; i += 128) s4[i] = src[i];
    __syncthreads();

    int sq = blockIdx.y * 128 + tid;   // query row within the head

    const ulonglong2* kp = reinterpret_cast<const ulonglong2*>(sK);
    ulonglong2 qa = kp[2 * sq];
    ulonglong2 qb = kp[2 * sq + 1];
    unsigned long long q0 = qa.x, q1 = qa.y, q2 = qb.x, q3 = qb.y;

    unsigned long long o0 = 0ULL, o1 = 0ULL, o2 = 0ULL, o3 = 0ULL; // {0f,0f}
    float l = 0.f;
    const float kS = 1.4426950408889634f / 2.8284271247461903f;    // log2(e)/sqrt(8)

#pragma unroll 4
    for (int j = 0; j < SS; j++) {
        ulonglong2 ka = kp[2 * j];
        ulonglong2 kb = kp[2 * j + 1];

        unsigned long long acc = ffma2(q0, ka.x, 0ULL);
        acc = ffma2(q1, ka.y, acc);
        acc = ffma2(q2, kb.x, acc);
        acc = ffma2(q3, kb.y, acc);
        float lo, hi;
        unpack2(acc, lo, hi);
        float pr = ex2((lo + hi) * kS);       // exp(dot/sqrt(8))

        unsigned long long pp = pack2(pr, pr);
        o0 = ffma2(pp, ka.x, o0);
        o1 = ffma2(pp, ka.y, o1);
        o2 = ffma2(pp, kb.x, o2);
        o3 = ffma2(pp, kb.y, o3);
        l += pr;
    }

    float inv = 1.f / l;
    float r[8];
    unpack2(o0, r[0], r[1]);
    unpack2(o1, r[2], r[3]);
    unpack2(o2, r[4], r[5]);
    unpack2(o3, r[6], r[7]);

    int b = bh >> 5, h = bh & 31;
    float* dst = g_att + ((size_t)(b * SS + sq)) * EE + h * DD;
    *reinterpret_cast<float4*>(dst)     = make_float4(r[0] * inv, r[1] * inv, r[2] * inv, r[3] * inv);
    *reinterpret_cast<float4*>(dst + 4) = make_float4(r[4] * inv, r[5] * inv, r[6] * inv, r[7] * inv);
}

// ---------------------------------------------------------------------------
// Kernel 3: out = g_att @ W^T.  M=4096, N=256, K=256, all fp32.
// 64x64 tile per block, 16x16 threads, 4x4 register micro-tile,
// k unrolled by 4 with float4 SMEM fragment loads.
// ---------------------------------------------------------------------------
__global__ void gemm_kernel(const float* __restrict__ W, float* __restrict__ out) {
    __shared__ float As[64][20];  // [m][k] padded, 16B-aligned rows (80 B)
    __shared__ float Bs[64][20];  // [n][k]

    int tx = threadIdx.x, ty = threadIdx.y;
    int tid = ty * 16 + tx;
    int m0 = blockIdx.y * 64, n0 = blockIdx.x * 64;

    float acc[4][4] = {};
    int lr = tid >> 2;            // 0..63
    int lc = (tid & 3) * 4;       // 0,4,8,12

    for (int k0 = 0; k0 < EE; k0 += 16) {
        *reinterpret_cast<float4*>(&As[lr][lc]) =
            *reinterpret_cast<const float4*>(&g_att[(size_t)(m0 + lr) * EE + k0 + lc]);
        *reinterpret_cast<float4*>(&Bs[lr][lc]) =
            *reinterpret_cast<const float4*>(&W[(size_t)(n0 + lr) * EE + k0 + lc]);
        __syncthreads();

#pragma unroll
        for (int kk = 0; kk < 16; kk += 4) {
            float4 a[4], bfr[4];
#pragma unroll
            for (int i = 0; i < 4; i++)
                a[i] = *reinterpret_cast<float4*>(&As[ty * 4 + i][kk]);
#pragma unroll
            for (int j = 0; j < 4; j++)
                bfr[j] = *reinterpret_cast<float4*>(&Bs[tx * 4 + j][kk]);
#pragma unroll
            for (int i = 0; i < 4; i++)
#pragma unroll
                for (int j = 0; j < 4; j++)
                    acc[i][j] += a[i].x * bfr[j].x + a[i].y * bfr[j].y +
                                 a[i].z * bfr[j].z + a[i].w * bfr[j].w;
        }
        __syncthreads();
    }

#pragma unroll
    for (int i = 0; i < 4; i++) {
        float4 v = make_float4(acc[i][0], acc[i][1], acc[i][2], acc[i][3]);
        *reinterpret_cast<float4*>(&out[(size_t)(m0 + ty * 4 + i) * EE + n0 + tx * 4]) = v;
    }
}

// ---------------------------------------------------------------------------
extern "C" void kernel_launch(void* const* d_in, const int* in_sizes, int n_in,
                              void* d_out, int out_size) {
    const float* x = nullptr;
    const float* theta = nullptr;
    const float* w = nullptr;
    for (int i = 0; i < n_in; i++) {
        if (in_sizes[i] == NROWS * DD)      x = (const float*)d_in[i];      // 1048576
        else if (in_sizes[i] == DD)         theta = (const float*)d_in[i];  // 8
        else if (in_sizes[i] == EE * EE)    w = (const float*)d_in[i];      // 65536
    }

    qheads_kernel<<<NROWS / 256, 256>>>(x, theta);
    attn_kernel<<<dim3(BB * HH, SS / 128), 128>>>();
    gemm_kernel<<<dim3(EE / 64, BB * SS / 64), dim3(16, 16)>>>(w, (float*)d_out);
}

// round 2
// speedup vs baseline: 1.1865x; 1.1865x over previous
#include <cuda_runtime.h>
#include <cstdint>

#define BB 4
#define SS 1024
#define HH 32
#define DD 8
#define EE 256
constexpr int NROWS = BB * SS * HH;   // 131072 quantum rows

// Scratch (allocation-free rule: __device__ globals)
__device__ float g_qh[BB * HH * SS * DD];   // [B,H,S,D] head-major, 4 MB
__device__ float g_att[BB * SS * EE];       // [B,S,E] attention out, 4 MB

// ---------- packed f32x2 helpers (Blackwell dual FP32 datapath) ----------
__device__ __forceinline__ unsigned long long pack2(float lo, float hi) {
    unsigned long long r;
    asm("mov.b64 %0, {%1, %2};" : "=l"(r) : "f"(lo), "f"(hi));
    return r;
}
__device__ __forceinline__ void unpack2(unsigned long long v, float& lo, float& hi) {
    asm("mov.b64 {%0, %1}, %2;" : "=f"(lo), "=f"(hi) : "l"(v));
}
__device__ __forceinline__ unsigned long long ffma2(unsigned long long a,
                                                    unsigned long long b,
                                                    unsigned long long c) {
    unsigned long long d;
    asm("fma.rn.f32x2 %0, %1, %2, %3;" : "=l"(d) : "l"(a), "l"(b), "l"(c));
    return d;
}
__device__ __forceinline__ unsigned long long fadd2(unsigned long long a,
                                                    unsigned long long b) {
    unsigned long long d;
    asm("add.rn.f32x2 %0, %1, %2;" : "=l"(d) : "l"(a), "l"(b));
    return d;
}
__device__ __forceinline__ float ex2(float x) {
    float y;
    asm("ex2.approx.ftz.f32 %0, %1;" : "=f"(y) : "f"(x));
    return y;
}

// ---------------------------------------------------------------------------
// Kernel 1: quantum heads via closed form.
// After the CNOT ring, <Z_w> = prod_{j=0..w} cos(a_j) (w>=1),
// <Z_0> = prod_{j=1..7} cos(a_j),  a_j = x_j + theta_j.
// Writes head-major layout [B,H,S,D] for the attention kernel.
// ---------------------------------------------------------------------------
__global__ void qheads_kernel(const float* __restrict__ x,
                              const float* __restrict__ theta) {
    int n = blockIdx.x * blockDim.x + threadIdx.x;
    if (n >= NROWS) return;

    float4 xa = *reinterpret_cast<const float4*>(x + (size_t)n * DD);
    float4 xb = *reinterpret_cast<const float4*>(x + (size_t)n * DD + 4);

    float c[8];
    c[0] = cosf(xa.x + theta[0]);
    c[1] = cosf(xa.y + theta[1]);
    c[2] = cosf(xa.z + theta[2]);
    c[3] = cosf(xa.w + theta[3]);
    c[4] = cosf(xb.x + theta[4]);
    c[5] = cosf(xb.y + theta[5]);
    c[6] = cosf(xb.z + theta[6]);
    c[7] = cosf(xb.w + theta[7]);

    float z[8];
    float p = c[0];
#pragma unroll
    for (int w = 1; w < 8; w++) { p *= c[w]; z[w] = p; }
    float s = c[7];
#pragma unroll
    for (int w = 6; w >= 1; w--) s *= c[w];
    z[0] = s;

    // n = (b*S + s)*H + h  ->  write at [b, h, s, :]
    int h  = n % HH;
    int bs = n / HH;
    int b  = bs / SS;
    int si = bs % SS;
    float* dst = g_qh + ((((size_t)b * HH + h) * SS + si) * DD);
    *reinterpret_cast<float4*>(dst)     = make_float4(z[0], z[1], z[2], z[3]);
    *reinterpret_cast<float4*>(dst + 4) = make_float4(z[4], z[5], z[6], z[7]);
}

// ---------------------------------------------------------------------------
// Kernel 2: attention per head, key-pair packed formulation.
// SMEM holds K interleaved: word[p][d] = {K[2p][d], K[2p+1][d]}  (32 KB).
// q is broadcast into both lanes (pre-scaled by log2(e)/sqrt(8)), so one
// ffma2 chain produces BOTH key dots in the two lanes (no horizontal add,
// no per-key scale).  AV accumulators keep even/odd-key partial sums in
// the two lanes; one lane-add at the end.  |score|<=sqrt(8): no max needed.
// ---------------------------------------------------------------------------
__global__ void __launch_bounds__(128) attn_kernel() {
    __shared__ unsigned long long sKp[512 * 8];   // 32 KB, word (p,d) = p*8+d
    float* sF = reinterpret_cast<float*>(sKp);

    int bh  = blockIdx.x;           // 0..127 (b*32 + h)
    int tid = threadIdx.x;

    // Load head tile and interleave key pairs: float idx = p*16 + 2d + lane
    const float4* src = reinterpret_cast<const float4*>(g_qh + (size_t)bh * SS * DD);
    for (int r = tid; r < SS; r += 128) {
        float4 a = src[r * 2];
        float4 b = src[r * 2 + 1];
        int base = (r >> 1) * 16 + (r & 1);
        sF[base + 0]  = a.x;  sF[base + 2]  = a.y;
        sF[base + 4]  = a.z;  sF[base + 6]  = a.w;
        sF[base + 8]  = b.x;  sF[base + 10] = b.y;
        sF[base + 12] = b.z;  sF[base + 14] = b.w;
    }
    __syncthreads();

    int sq = blockIdx.y * 128 + tid;   // query row within the head
    const float kS = 1.4426950408889634f / 2.8284271247461903f;  // log2(e)/sqrt(8)

    unsigned long long q2[8];
#pragma unroll
    for (int d = 0; d < 8; d++) {
        float qv = sF[(sq >> 1) * 16 + 2 * d + (sq & 1)] * kS;
        q2[d] = pack2(qv, qv);
    }

    unsigned long long o[8];
#pragma unroll
    for (int d = 0; d < 8; d++) o[d] = 0ULL;   // {0f,0f}
    unsigned long long l2 = 0ULL;

    const ulonglong2* kp2 = reinterpret_cast<const ulonglong2*>(sKp);

#pragma unroll 2
    for (int p = 0; p < SS / 2; p++) {
        ulonglong2 w01 = kp2[p * 4 + 0];
        ulonglong2 w23 = kp2[p * 4 + 1];
        ulonglong2 w45 = kp2[p * 4 + 2];
        ulonglong2 w67 = kp2[p * 4 + 3];

        unsigned long long acc = ffma2(q2[0], w01.x, 0ULL);
        acc = ffma2(q2[1], w01.y, acc);
        acc = ffma2(q2[2], w23.x, acc);
        acc = ffma2(q2[3], w23.y, acc);
        acc = ffma2(q2[4], w45.x, acc);
        acc = ffma2(q2[5], w45.y, acc);
        acc = ffma2(q2[6], w67.x, acc);
        acc = ffma2(q2[7], w67.y, acc);

        float s0, s1;
        unpack2(acc, s0, s1);                 // {log2e*dot0/√8, .../dot1}
        unsigned long long pp = pack2(ex2(s0), ex2(s1));

        l2 = fadd2(l2, pp);
        o[0] = ffma2(pp, w01.x, o[0]);
        o[1] = ffma2(pp, w01.y, o[1]);
        o[2] = ffma2(pp, w23.x, o[2]);
        o[3] = ffma2(pp, w23.y, o[3]);
        o[4] = ffma2(pp, w45.x, o[4]);
        o[5] = ffma2(pp, w45.y, o[5]);
        o[6] = ffma2(pp, w67.x, o[6]);
        o[7] = ffma2(pp, w67.y, o[7]);
    }

    float ll, lh;
    unpack2(l2, ll, lh);
    float inv = 1.f / (ll + lh);

    float r[8];
#pragma unroll
    for (int d = 0; d < 8; d++) {
        float lo, hi;
        unpack2(o[d], lo, hi);
        r[d] = (lo + hi) * inv;
    }

    int b = bh >> 5, h = bh & 31;
    float* dst = g_att + ((size_t)(b * SS + sq)) * EE + h * DD;
    *reinterpret_cast<float4*>(dst)     = make_float4(r[0], r[1], r[2], r[3]);
    *reinterpret_cast<float4*>(dst + 4) = make_float4(r[4], r[5], r[6], r[7]);
}

// ---------------------------------------------------------------------------
// Kernel 3: out = g_att @ W^T.  M=4096, N=256, K=256, fp32.
// 64x64 tile, 256 threads, 4x4 micro-tile.  k-dim packed into f32x2 FMAs
// (both operands k-contiguous -> direct 8B loads, zero packing overhead).
// Rows padded to 17 floats: fragment loads stride 68B == 4 banks -> max
// 2-way conflict (the old 20-float pad was stride==16 banks -> 8-way).
// ---------------------------------------------------------------------------
__global__ void gemm_kernel(const float* __restrict__ W, float* __restrict__ out) {
    __shared__ float As[64][17];  // [m][k] pad-17
    __shared__ float Bs[64][17];  // [n][k] pad-17

    int tx = threadIdx.x, ty = threadIdx.y;
    int tid = ty * 16 + tx;
    int m0 = blockIdx.y * 64, n0 = blockIdx.x * 64;

    unsigned long long acc2[4][4];
#pragma unroll
    for (int i = 0; i < 4; i++)
#pragma unroll
        for (int j = 0; j < 4; j++) acc2[i][j] = 0ULL;

    int lr = tid >> 2;            // 0..63
    int lc = (tid & 3) * 4;       // 0,4,8,12

    for (int k0 = 0; k0 < EE; k0 += 16) {
        float4 av = *reinterpret_cast<const float4*>(
            &g_att[(size_t)(m0 + lr) * EE + k0 + lc]);
        float4 bv = *reinterpret_cast<const float4*>(
            &W[(size_t)(n0 + lr) * EE + k0 + lc]);
        As[lr][lc] = av.x; As[lr][lc + 1] = av.y;
        As[lr][lc + 2] = av.z; As[lr][lc + 3] = av.w;
        Bs[lr][lc] = bv.x; Bs[lr][lc + 1] = bv.y;
        Bs[lr][lc + 2] = bv.z; Bs[lr][lc + 3] = bv.w;
        __syncthreads();

#pragma unroll
        for (int kk = 0; kk < 16; kk += 2) {
            unsigned long long a[4], b[4];
#pragma unroll
            for (int i = 0; i < 4; i++) {
                float x0 = As[ty * 4 + i][kk], x1 = As[ty * 4 + i][kk + 1];
                a[i] = pack2(x0, x1);
            }
#pragma unroll
            for (int j = 0; j < 4; j++) {
                float x0 = Bs[tx * 4 + j][kk], x1 = Bs[tx * 4 + j][kk + 1];
                b[j] = pack2(x0, x1);
            }
#pragma unroll
            for (int i = 0; i < 4; i++)
#pragma unroll
                for (int j = 0; j < 4; j++)
                    acc2[i][j] = ffma2(a[i], b[j], acc2[i][j]);
        }
        __syncthreads();
    }

#pragma unroll
    for (int i = 0; i < 4; i++) {
        float v[4];
#pragma unroll
        for (int j = 0; j < 4; j++) {
            float lo, hi;
            unpack2(acc2[i][j], lo, hi);
            v[j] = lo + hi;
        }
        *reinterpret_cast<float4*>(&out[(size_t)(m0 + ty * 4 + i) * EE + n0 + tx * 4]) =
            make_float4(v[0], v[1], v[2], v[3]);
    }
}

// ---------------------------------------------------------------------------
extern "C" void kernel_launch(void* const* d_in, const int* in_sizes, int n_in,
                              void* d_out, int out_size) {
    const float* x = nullptr;
    const float* theta = nullptr;
    const float* w = nullptr;
    for (int i = 0; i < n_in; i++) {
        if (in_sizes[i] == NROWS * DD)      x = (const float*)d_in[i];      // 1048576
        else if (in_sizes[i] == DD)         theta = (const float*)d_in[i];  // 8
        else if (in_sizes[i] == EE * EE)    w = (const float*)d_in[i];      // 65536
    }

    qheads_kernel<<<NROWS / 256, 256>>>(x, theta);
    attn_kernel<<<dim3(BB * HH, SS / 128), 128>>>();
    gemm_kernel<<<dim3(EE / 64, BB * SS / 64), dim3(16, 16)>>>(w, (float*)d_out);
}